// round 15
// baseline (speedup 1.0000x reference)
#include <cuda_runtime.h>
#include <cuda_bf16.h>
#include <math.h>
#include <float.h>
#include <stdint.h>

// ---------------- problem constants ----------------
#define NN 20000
#define NP 20096            // NN padded to 128
#define EE 320000
#define MEM 128
#define INC 256
#define HH 2
#define CC 128
#define ED 200
#define TD 100
#define NLAYER 3
#define QROW 1440           // qkvs row: q|k|v|sk|U0|U1 (+pad)

static __device__ __constant__ float RSQRT_C = 0.08838834764831845f;

// ---------------- scratch (zero-initialized .bss pads are load-bearing) ----------------
__device__ float g_te   [(size_t)EE * TD];
__device__ float g_h    [(size_t)NN * INC];
__device__ float g_qkvs [(size_t)NN * QROW];
__device__ float g_agg  [(size_t)NN * INC];
__device__ int   g_deg [NN];
__device__ int   g_cnt [NN];
__device__ int   g_rowptr[NN + 1];
__device__ int2  g_epair[EE];
__device__ float g_bpack [(size_t)NLAYER * 1536];
// packed bf16 hi/lo pair buffers
__device__ uint32_t g_WTh [(size_t)NLAYER * 1536 * 128], g_WTm [(size_t)NLAYER * 1536 * 128];
__device__ uint32_t g_linTh[(size_t)256 * 64],           g_linTm[(size_t)256 * 64];
__device__ uint32_t g_WeTh[(size_t)NLAYER * 256 * 128],  g_WeTm[(size_t)NLAYER * 256 * 128];
__device__ uint32_t g_xH  [(size_t)NP * 64],             g_xM  [(size_t)NP * 64];
__device__ uint32_t g_hH  [(size_t)NP * 128],            g_hM  [(size_t)NP * 128];
__device__ uint32_t g_sH  [(size_t)2 * NP * 128],        g_sM  [(size_t)2 * NP * 128];

// ---------------- helpers ----------------
__device__ __forceinline__ uint32_t smem_u32(const void* p) {
    uint32_t a;
    asm("{ .reg .u64 t; cvta.to.shared.u64 t, %1; cvt.u32.u64 %0, t; }" : "=r"(a) : "l"(p));
    return a;
}
__device__ __forceinline__ uint32_t pack_hi(float x, float y) {
    __nv_bfloat162 p = __floats2bfloat162_rn(x, y);
    return *(uint32_t*)&p;
}
__device__ __forceinline__ uint32_t pack_mid(float x, float y) {
    __nv_bfloat16 hx = __float2bfloat16(x);
    __nv_bfloat16 hy = __float2bfloat16(y);
    __nv_bfloat162 p = __floats2bfloat162_rn(x - __bfloat162float(hx),
                                             y - __bfloat162float(hy));
    return *(uint32_t*)&p;
}
__device__ __forceinline__ void mma_bf16(float* c, const uint32_t* a,
                                         uint32_t b0, uint32_t b1) {
    asm volatile(
        "mma.sync.aligned.m16n8k16.row.col.f32.bf16.bf16.f32 "
        "{%0,%1,%2,%3}, {%4,%5,%6,%7}, {%8,%9}, {%0,%1,%2,%3};"
        : "+f"(c[0]), "+f"(c[1]), "+f"(c[2]), "+f"(c[3])
        : "r"(a[0]), "r"(a[1]), "r"(a[2]), "r"(a[3]), "r"(b0), "r"(b1));
}
__device__ __forceinline__ void ldsm4(uint32_t* r, uint32_t addr) {
    asm volatile("ldmatrix.sync.aligned.m8n8.x4.shared.b16 {%0,%1,%2,%3}, [%4];"
                 : "=r"(r[0]), "=r"(r[1]), "=r"(r[2]), "=r"(r[3]) : "r"(addr));
}
#define CP_ASYNC16(dst, src) \
    asm volatile("cp.async.cg.shared.global [%0], [%1], 16;" :: "r"(dst), "l"(src) : "memory")
#define CP_COMMIT asm volatile("cp.async.commit_group;" ::: "memory")
#define CP_WAIT1  asm volatile("cp.async.wait_group 1;" ::: "memory")

// fast accurate cos: Cody-Waite 2pi reduction + __cosf on reduced arg
__device__ __forceinline__ float fast_cos(float a) {
    const float INV2PI = 0.15915494309189535f;
    const float C1 = 6.28318548202514648f;
    const float C2 = -1.74845553e-7f;
    float k = rintf(a * INV2PI);
    float r = fmaf(-k, C1, a);
    r = fmaf(-k, C2, r);
    return __cosf(r);
}

// ---------------- HMMA 3xBF16 GEMM, BK=64, templated on BN (128 or 256) ----------------
template<int BN>
__global__ __launch_bounds__(512)
void tc_gemm(int M, int N, int K2,
             const uint32_t* __restrict__ AH, const uint32_t* __restrict__ AM,
             int lda2, int aZ,
             const uint32_t* __restrict__ BH, const uint32_t* __restrict__ BM,
             int ldb2, int bZ,
             const float* __restrict__ bias,
             float* __restrict__ C, int ldc, int cZ, int accum,
             uint32_t* __restrict__ auxH, uint32_t* __restrict__ auxM, int ldaux2,
             int auxN) {
    extern __shared__ uint32_t smem[];
    constexpr int NGRP = BN / 64;
    constexpr uint32_t STAGE = (128 + BN) * 256;
    const int tid = threadIdx.x;
    const int wid = tid >> 5;
    const int lane = tid & 31;
    const int wm = wid & 3;
    const int wn = wid >> 2;
    const int m0 = blockIdx.y * 128;
    const int n0 = blockIdx.x * BN;
    const int z = blockIdx.z;
    AH += (size_t)z * aZ; AM += (size_t)z * aZ;
    BH += (size_t)z * bZ; BM += (size_t)z * bZ;
    C  += (size_t)z * cZ;

    uint32_t sbase = smem_u32(smem);

    float c[2][2 * NGRP][4];
#pragma unroll
    for (int i = 0; i < 2; i++)
#pragma unroll
        for (int j = 0; j < 2 * NGRP; j++)
#pragma unroll
            for (int l = 0; l < 4; l++) c[i][j][l] = 0.f;

    const int nc = K2 >> 5;
    const uint32_t l7 = (uint32_t)(lane & 7);
    const uint32_t asel = (uint32_t)(lane >> 4);
    uint32_t aRowB[2];
#pragma unroll
    for (int mt = 0; mt < 2; mt++)
        aRowB[mt] = (uint32_t)(wm * 32 + mt * 16 + (lane & 15)) * 256u;
    const uint32_t bkb = (uint32_t)((lane >> 3) & 1);
    const uint32_t bOff0 = (uint32_t)(wn * (BN / 4) + (lane >> 4) * 8 + (int)l7) * 256u;

#define ISSUE(CH)                                                               \
    do {                                                                        \
        int k0p = (CH) << 5;                                                    \
        uint32_t stOff = (uint32_t)((CH) & 1) * STAGE;                          \
        _Pragma("unroll")                                                       \
        for (int it = 0; it < (128 + BN) / 32; it++) {                          \
            int idx = tid + it * 512;                                           \
            int row = idx >> 4;                                                 \
            int sb = idx & 15;                                                  \
            const uint32_t* S;                                                  \
            size_t rowOff;                                                      \
            if (row < 128) { S = (sb >> 3) ? AM : AH; rowOff = (size_t)(m0 + row) * lda2; } \
            else           { S = (sb >> 3) ? BM : BH; rowOff = (size_t)(n0 + row - 128) * ldb2; } \
            int pb = sb ^ (row & 7);                                            \
            CP_ASYNC16(sbase + stOff + (uint32_t)row * 256u + (uint32_t)pb * 16u, \
                       S + rowOff + k0p + (sb & 7) * 4);                        \
        }                                                                       \
    } while (0)

    ISSUE(0);
    CP_COMMIT;
    for (int ch = 0; ch < nc; ch++) {
        if (ch + 1 < nc) ISSUE(ch + 1);
        CP_COMMIT;
        CP_WAIT1;
        __syncthreads();
        const uint32_t Ab = sbase + (uint32_t)(ch & 1) * STAGE;
        const uint32_t Bb = Ab + 32768u;
#pragma unroll
        for (int ks = 0; ks < 4; ks++) {
            uint32_t abH = (asel + 2u * (uint32_t)ks) ^ l7;
            uint32_t abM = abH ^ 8u;
            uint32_t ah[2][4], am_[2][4];
#pragma unroll
            for (int mt = 0; mt < 2; mt++) {
                ldsm4(ah[mt],  Ab + aRowB[mt] + (abH << 4));
                ldsm4(am_[mt], Ab + aRowB[mt] + (abM << 4));
            }
            uint32_t bbH = (bkb + 2u * (uint32_t)ks) ^ l7;
            uint32_t bbM = bbH ^ 8u;
#pragma unroll
            for (int p2 = 0; p2 < NGRP; p2++) {
                uint32_t bh[4], bm[4];
                uint32_t bb = Bb + bOff0 + (uint32_t)p2 * 4096u;
                ldsm4(bh, bb + (bbH << 4));
                ldsm4(bm, bb + (bbM << 4));
#pragma unroll
                for (int sub = 0; sub < 2; sub++) {
                    int nt = 2 * p2 + sub;
                    uint32_t bh0 = bh[2 * sub], bh1 = bh[2 * sub + 1];
                    uint32_t bm0 = bm[2 * sub], bm1 = bm[2 * sub + 1];
#pragma unroll
                    for (int mt = 0; mt < 2; mt++) {
                        mma_bf16(c[mt][nt], ah[mt], bh0, bh1);
                        mma_bf16(c[mt][nt], ah[mt], bm0, bm1);
                        mma_bf16(c[mt][nt], am_[mt], bh0, bh1);
                    }
                }
            }
        }
        __syncthreads();
    }
#undef ISSUE

#pragma unroll
    for (int mt = 0; mt < 2; mt++) {
        int row0 = m0 + wm * 32 + mt * 16 + (lane >> 2);
#pragma unroll
        for (int nt = 0; nt < 2 * NGRP; nt++) {
            int col = n0 + wn * (BN / 4) + nt * 8 + 2 * (lane & 3);
            if (col >= N) continue;
#pragma unroll
            for (int half = 0; half < 2; half++) {
                int row = row0 + 8 * half;
                if (row >= M) continue;
                float v0 = c[mt][nt][2 * half];
                float v1 = c[mt][nt][2 * half + 1];
                if (bias) { v0 += bias[col]; v1 += bias[col + 1]; }
                size_t off = (size_t)row * ldc + col;
                if (accum) { v0 += C[off]; v1 += C[off + 1]; }
                C[off] = v0;
                C[off + 1] = v1;
                if (auxH && col < auxN) {
                    size_t po = (size_t)row * ldaux2 + (col >> 1);
                    auxH[po] = pack_hi(v0, v1);
                    auxM[po] = pack_mid(v0, v1);
                }
            }
        }
    }
}

// ---------------- composite U weights: WU[k, h*200+j] = sum_c Wq[k,h*128+c]*We[j,h*128+c]
__global__ void k_wu(const float* __restrict__ Wq, const float* __restrict__ bq,
                     const float* __restrict__ We) {
    const int T1 = NLAYER * 2 * 200 * 128;
    int idx = blockIdx.x * blockDim.x + threadIdx.x;
    if (idx < T1) {
        int L = idx / (2 * 200 * 128);
        int rem = idx - L * (2 * 200 * 128);
        int h = rem / (200 * 128);
        rem -= h * 200 * 128;
        int j = rem >> 7, p = rem & 127;
        const float* wq = Wq + (size_t)L * 65536 + h * 128;
        const float* we = We + (size_t)L * 51200 + (size_t)j * 256 + h * 128;
        float v0 = 0.f, v1 = 0.f;
        for (int cc = 0; cc < 128; cc++) {
            float w = we[cc];
            v0 = fmaf(wq[(size_t)(2 * p) * 256 + cc], w, v0);
            v1 = fmaf(wq[(size_t)(2 * p + 1) * 256 + cc], w, v1);
        }
        size_t o = ((size_t)L * 1536 + 1024 + h * 200 + j) * 128 + p;
        g_WTh[o] = pack_hi(v0, v1);
        g_WTm[o] = pack_mid(v0, v1);
        return;
    }
    idx -= T1;
    if (idx < NLAYER * 400) {  // bias: bU[j] = sum_c bq[h*128+c]*We[j,h*128+c]
        int L = idx / 400;
        int rem = idx - L * 400;
        int h = rem / 200, j = rem - h * 200;
        const float* we = We + (size_t)L * 51200 + (size_t)j * 256 + h * 128;
        const float* bb = bq + L * 256 + h * 128;
        float v = 0.f;
        for (int cc = 0; cc < 128; cc++) v = fmaf(bb[cc], we[cc], v);
        g_bpack[(size_t)L * 1536 + 1024 + h * 200 + j] = v;
    }
}

// ---------------- weight / input pre-split ----------------
__global__ void k_prep(const float* __restrict__ Wq, const float* __restrict__ Wk,
                       const float* __restrict__ Wv, const float* __restrict__ Wsk,
                       const float* __restrict__ bq, const float* __restrict__ bk,
                       const float* __restrict__ bv, const float* __restrict__ bsk,
                       const float* __restrict__ lin_w, const float* __restrict__ We,
                       const float* __restrict__ x) {
    const int R1 = NLAYER * 1024 * 128;
    const int R2 = NLAYER * 1024;
    const int R3 = 256 * 64;
    const int R5 = NLAYER * 256 * 100;
    const int R6 = NN * 64;
    int total = R1 + R2 + R3 + R5 + R6;
    for (int idx = blockIdx.x * blockDim.x + threadIdx.x; idx < total;
         idx += gridDim.x * blockDim.x) {
        int i = idx;
        if (i < R1) {
            int L = i / (1024 * 128);
            int rem = i - L * 1024 * 128;
            int row = rem >> 7, p = rem & 127;
            int which = row >> 8, n = row & 255;
            const float* W = (which == 0) ? Wq : (which == 1) ? Wk : (which == 2) ? Wv : Wsk;
            float v0 = W[(size_t)L * 65536 + (size_t)(2 * p) * 256 + n];
            float v1 = W[(size_t)L * 65536 + (size_t)(2 * p + 1) * 256 + n];
            size_t o = ((size_t)L * 1536 + row) * 128 + p;
            g_WTh[o] = pack_hi(v0, v1);
            g_WTm[o] = pack_mid(v0, v1);
            continue;
        }
        i -= R1;
        if (i < R2) {
            int L = i / 1024, row = i - L * 1024;
            int which = row >> 8, n = row & 255;
            const float* bb = (which == 0) ? bq : (which == 1) ? bk : (which == 2) ? bv : bsk;
            g_bpack[(size_t)L * 1536 + row] = bb[L * 256 + n];
            continue;
        }
        i -= R2;
        if (i < R3) {
            int n = i >> 6, p = i & 63;
            float v0 = lin_w[(size_t)(2 * p) * 256 + n];
            float v1 = lin_w[(size_t)(2 * p + 1) * 256 + n];
            g_linTh[i] = pack_hi(v0, v1);
            g_linTm[i] = pack_mid(v0, v1);
            continue;
        }
        i -= R3;
        if (i < R5) {
            int L = i / (256 * 100);
            int rem = i - L * 256 * 100;
            int cch = rem / 100, p = rem - cch * 100;
            float v0 = We[(size_t)L * 51200 + (size_t)(2 * p) * 256 + cch];
            float v1 = We[(size_t)L * 51200 + (size_t)(2 * p + 1) * 256 + cch];
            size_t o = ((size_t)L * 256 + cch) * 128 + p;
            g_WeTh[o] = pack_hi(v0, v1);
            g_WeTm[o] = pack_mid(v0, v1);
            continue;
        }
        i -= R5;
        {
            int m = i >> 6, p = i & 63;
            float v0 = x[(size_t)m * 128 + 2 * p];
            float v1 = x[(size_t)m * 128 + 2 * p + 1];
            g_xH[i] = pack_hi(v0, v1);
            g_xM[i] = pack_mid(v0, v1);
        }
    }
}

// ---------------- CSR construction ----------------
__global__ void k_zero_int() {
    int i = blockIdx.x * blockDim.x + threadIdx.x;
    if (i < NN) { g_deg[i] = 0; g_cnt[i] = 0; }
}
__global__ void k_count(const int* __restrict__ dst) {
    int e = blockIdx.x * blockDim.x + threadIdx.x;
    if (e < EE) atomicAdd(&g_deg[dst[e]], 1);
}
__global__ void k_scan() {
    __shared__ int wsum[32];
    int tid = threadIdx.x;
    int lane = tid & 31;
    int wid = tid >> 5;
    int carry = 0;
    for (int base = 0; base < NN; base += 1024) {
        int i = base + tid;
        int x = (i < NN) ? g_deg[i] : 0;
#pragma unroll
        for (int o = 1; o < 32; o <<= 1) {
            int y = __shfl_up_sync(0xffffffffu, x, o);
            if (lane >= o) x += y;
        }
        if (lane == 31) wsum[wid] = x;
        __syncthreads();
        if (wid == 0) {
            int s = wsum[lane];
#pragma unroll
            for (int o = 1; o < 32; o <<= 1) {
                int y = __shfl_up_sync(0xffffffffu, s, o);
                if (lane >= o) s += y;
            }
            wsum[lane] = s;
        }
        __syncthreads();
        int off = (wid > 0) ? wsum[wid - 1] : 0;
        if (i < NN) g_rowptr[i + 1] = carry + off + x;
        carry += wsum[31];
        __syncthreads();
    }
    if (tid == 0) g_rowptr[0] = 0;
}
__global__ void k_place(const int* __restrict__ src, const int* __restrict__ dst) {
    int e = blockIdx.x * blockDim.x + threadIdx.x;
    if (e < EE) {
        int d = dst[e];
        int p = atomicAdd(&g_cnt[d], 1);
        g_epair[g_rowptr[d] + p] = make_int2(e, src[e]);
    }
}

// ---------------- time-encoding features ----------------
__global__ void k_te(const int* __restrict__ src,
                     const float* __restrict__ last_update,
                     const float* __restrict__ t,
                     const float* __restrict__ time_w,
                     const float* __restrict__ time_b) {
    int e = (blockIdx.x * blockDim.x + threadIdx.x) >> 5;
    int lane = threadIdx.x & 31;
    if (e >= EE) return;
    float rt = last_update[src[e]] - t[e];
    if (lane < 25) {
        float4 w = ((const float4*)time_w)[lane];
        float4 b = ((const float4*)time_b)[lane];
        float4 o;
        o.x = fast_cos(fmaf(rt, w.x, b.x));
        o.y = fast_cos(fmaf(rt, w.y, b.y));
        o.z = fast_cos(fmaf(rt, w.z, b.z));
        o.w = fast_cos(fmaf(rt, w.w, b.w));
        ((float4*)(g_te + (size_t)e * TD))[lane] = o;
    }
}

// ---------------- fused edge phase: warp per node, both heads, 2-edge unrolled ----
__global__ __launch_bounds__(256)
void k_edge(const float* __restrict__ msg) {
    int n = (blockIdx.x * blockDim.x + threadIdx.x) >> 5;
    int lane = threadIdx.x & 31;
    if (n >= NN) return;
    int b = g_rowptr[n], e_ = g_rowptr[n + 1];

    const float* qr = g_qkvs + (size_t)n * QROW;
    float q[8];
#pragma unroll
    for (int i = 0; i < 8; i++) q[i] = qr[lane + 32 * i];
    const float* Ur = qr + 1024;
    float u0[7], u1[7];
#pragma unroll
    for (int i = 0; i < 7; i++) {
        int j = lane + 32 * i;
        u0[i] = (j < ED) ? Ur[j] : 0.f;
        u1[i] = (j < ED) ? Ur[ED + j] : 0.f;
    }

    float m0 = -FLT_MAX, m1 = -FLT_MAX, d0 = 0.f, d1 = 0.f;
    float vacc[8], s0[7], s1[7];
#pragma unroll
    for (int i = 0; i < 8; i++) vacc[i] = 0.f;
#pragma unroll
    for (int i = 0; i < 7; i++) { s0[i] = 0.f; s1[i] = 0.f; }

    int jj = b;
    for (; jj + 1 < e_; jj += 2) {
        int2 pA = g_epair[jj], pB = g_epair[jj + 1];
        int eA = pA.x, sA = pA.y;
        int eB = pB.x, sB = pB.y;
        const float* krA = g_qkvs + (size_t)sA * QROW + 256;
        const float* krB = g_qkvs + (size_t)sB * QROW + 256;
        float kvA[8], kvB[8], vvA[8], vvB[8], erA[7], erB[7];
#pragma unroll
        for (int i = 0; i < 8; i++) {
            kvA[i] = krA[lane + 32 * i];
            kvB[i] = krB[lane + 32 * i];
            vvA[i] = krA[256 + lane + 32 * i];
            vvB[i] = krB[256 + lane + 32 * i];
        }
        const float* teA = g_te + (size_t)eA * TD;
        const float* teB = g_te + (size_t)eB * TD;
        const float* mgA = msg + (size_t)eA * TD;
        const float* mgB = msg + (size_t)eB * TD;
#pragma unroll
        for (int i = 0; i < 7; i++) {
            int j = lane + 32 * i;
            erA[i] = (j < ED) ? ((j < TD) ? teA[j] : mgA[j - TD]) : 0.f;
            erB[i] = (j < ED) ? ((j < TD) ? teB[j] : mgB[j - TD]) : 0.f;
        }
        float aA0 = 0.f, aA1 = 0.f, aB0 = 0.f, aB1 = 0.f;
#pragma unroll
        for (int i = 0; i < 4; i++) {
            aA0 += q[i] * kvA[i];       aA1 += q[i + 4] * kvA[i + 4];
            aB0 += q[i] * kvB[i];       aB1 += q[i + 4] * kvB[i + 4];
        }
#pragma unroll
        for (int i = 0; i < 7; i++) {
            aA0 += erA[i] * u0[i];      aA1 += erA[i] * u1[i];
            aB0 += erB[i] * u0[i];      aB1 += erB[i] * u1[i];
        }
#pragma unroll
        for (int o = 16; o; o >>= 1) {
            aA0 += __shfl_xor_sync(0xffffffffu, aA0, o);
            aA1 += __shfl_xor_sync(0xffffffffu, aA1, o);
            aB0 += __shfl_xor_sync(0xffffffffu, aB0, o);
            aB1 += __shfl_xor_sync(0xffffffffu, aB1, o);
        }
        aA0 *= RSQRT_C; aA1 *= RSQRT_C; aB0 *= RSQRT_C; aB1 *= RSQRT_C;

        float mn0 = fmaxf(m0, fmaxf(aA0, aB0));
        float sc0 = expf(m0 - mn0);
        float wA0 = expf(aA0 - mn0);
        float wB0 = expf(aB0 - mn0);
        d0 = d0 * sc0 + wA0 + wB0;
        m0 = mn0;
        float mn1 = fmaxf(m1, fmaxf(aA1, aB1));
        float sc1 = expf(m1 - mn1);
        float wA1 = expf(aA1 - mn1);
        float wB1 = expf(aB1 - mn1);
        d1 = d1 * sc1 + wA1 + wB1;
        m1 = mn1;
#pragma unroll
        for (int i = 0; i < 4; i++) {
            vacc[i]     = vacc[i]     * sc0 + wA0 * vvA[i]     + wB0 * vvB[i];
            vacc[i + 4] = vacc[i + 4] * sc1 + wA1 * vvA[i + 4] + wB1 * vvB[i + 4];
        }
#pragma unroll
        for (int i = 0; i < 7; i++) {
            s0[i] = s0[i] * sc0 + wA0 * erA[i] + wB0 * erB[i];
            s1[i] = s1[i] * sc1 + wA1 * erA[i] + wB1 * erB[i];
        }
    }
    if (jj < e_) {
        int2 pA = g_epair[jj];
        int eA = pA.x, sA = pA.y;
        const float* krA = g_qkvs + (size_t)sA * QROW + 256;
        float kvA[8], vvA[8], erA[7];
#pragma unroll
        for (int i = 0; i < 8; i++) {
            kvA[i] = krA[lane + 32 * i];
            vvA[i] = krA[256 + lane + 32 * i];
        }
        const float* teA = g_te + (size_t)eA * TD;
        const float* mgA = msg + (size_t)eA * TD;
#pragma unroll
        for (int i = 0; i < 7; i++) {
            int j = lane + 32 * i;
            erA[i] = (j < ED) ? ((j < TD) ? teA[j] : mgA[j - TD]) : 0.f;
        }
        float aA0 = 0.f, aA1 = 0.f;
#pragma unroll
        for (int i = 0; i < 4; i++) { aA0 += q[i] * kvA[i]; aA1 += q[i + 4] * kvA[i + 4]; }
#pragma unroll
        for (int i = 0; i < 7; i++) { aA0 += erA[i] * u0[i]; aA1 += erA[i] * u1[i]; }
#pragma unroll
        for (int o = 16; o; o >>= 1) {
            aA0 += __shfl_xor_sync(0xffffffffu, aA0, o);
            aA1 += __shfl_xor_sync(0xffffffffu, aA1, o);
        }
        aA0 *= RSQRT_C; aA1 *= RSQRT_C;
        float mn0 = fmaxf(m0, aA0);
        float sc0 = expf(m0 - mn0);
        float wA0 = expf(aA0 - mn0);
        d0 = d0 * sc0 + wA0;
        m0 = mn0;
        float mn1 = fmaxf(m1, aA1);
        float sc1 = expf(m1 - mn1);
        float wA1 = expf(aA1 - mn1);
        d1 = d1 * sc1 + wA1;
        m1 = mn1;
#pragma unroll
        for (int i = 0; i < 4; i++) {
            vacc[i]     = vacc[i]     * sc0 + wA0 * vvA[i];
            vacc[i + 4] = vacc[i + 4] * sc1 + wA1 * vvA[i + 4];
        }
#pragma unroll
        for (int i = 0; i < 7; i++) {
            s0[i] = s0[i] * sc0 + wA0 * erA[i];
            s1[i] = s1[i] * sc1 + wA1 * erA[i];
        }
    }

    float div0 = 1.f / (d0 + 1e-16f);
    float div1 = 1.f / (d1 + 1e-16f);
    float* ar = g_agg + (size_t)n * 256;
#pragma unroll
    for (int i = 0; i < 4; i++) {
        ar[lane + 32 * i]         = vacc[i] * div0;
        ar[lane + 32 * (i + 4)]   = vacc[i + 4] * div1;
    }
#pragma unroll
    for (int i = 0; i < 7; i++) {
        int j = lane + 32 * i;
        float v0 = (j < ED) ? s0[i] * div0 : 0.f;
        float v1 = (j < ED) ? s1[i] * div1 : 0.f;
        float v0b = __shfl_xor_sync(0xffffffffu, v0, 1);
        float v1b = __shfl_xor_sync(0xffffffffu, v1, 1);
        if (!(lane & 1) && j < ED) {
            size_t o0 = (size_t)n * 128 + (j >> 1);
            g_sH[o0] = pack_hi(v0, v0b);
            g_sM[o0] = pack_mid(v0, v0b);
            size_t o1 = ((size_t)NP + n) * 128 + (j >> 1);
            g_sH[o1] = pack_hi(v1, v1b);
            g_sM[o1] = pack_mid(v1, v1b);
        }
    }
}

// ---------------- residual + LayerNorm (+ SiLU, + bf16 pair emit) ----------------
__global__ void k_ln(const float* __restrict__ ln_g, const float* __restrict__ ln_b,
                     float* __restrict__ out, int silu) {
    int n = blockIdx.x;
    int c = threadIdx.x;
    size_t off = (size_t)n * INC + c;
    float pre = g_h[off] + g_agg[off] + g_qkvs[(size_t)n * QROW + 768 + c];
    __shared__ float red[INC];
    red[c] = pre;
    __syncthreads();
#pragma unroll
    for (int o = 128; o; o >>= 1) {
        if (c < o) red[c] += red[c + o];
        __syncthreads();
    }
    float mu = red[0] * (1.f / INC);
    __syncthreads();
    float dv = pre - mu;
    red[c] = dv * dv;
    __syncthreads();
#pragma unroll
    for (int o = 128; o; o >>= 1) {
        if (c < o) red[c] += red[c + o];
        __syncthreads();
    }
    float var = red[0] * (1.f / INC);
    float y = dv * rsqrtf(var + 1e-5f) * ln_g[c] + ln_b[c];
    if (silu) {
        y = y / (1.f + expf(-y));
        float y2 = __shfl_xor_sync(0xffffffffu, y, 1);
        out[off] = y;
        if (!(c & 1)) {
            size_t po = (size_t)n * 128 + (c >> 1);
            g_hH[po] = pack_hi(y, y2);
            g_hM[po] = pack_mid(y, y2);
        }
    } else {
        out[off] = y;
    }
}

// ---------------- host launcher ----------------
static inline void get_sym(void** p, const void* sym) { cudaGetSymbolAddress(p, sym); }

extern "C" void kernel_launch(void* const* d_in, const int* in_sizes, int n_in,
                              void* d_out, int out_size) {
    const float* x           = (const float*)d_in[0];
    const float* last_update = (const float*)d_in[1];
    const int*   edge_index  = (const int*)  d_in[2];
    const float* t           = (const float*)d_in[3];
    const float* msg         = (const float*)d_in[4];
    const float* time_w      = (const float*)d_in[5];
    const float* time_b      = (const float*)d_in[6];
    const float* lin_w       = (const float*)d_in[7];
    const float* lin_b       = (const float*)d_in[8];
    const float* Wq          = (const float*)d_in[9];
    const float* bq          = (const float*)d_in[10];
    const float* Wk          = (const float*)d_in[11];
    const float* bk          = (const float*)d_in[12];
    const float* Wv          = (const float*)d_in[13];
    const float* bv          = (const float*)d_in[14];
    const float* We          = (const float*)d_in[15];
    const float* Wsk         = (const float*)d_in[16];
    const float* bsk         = (const float*)d_in[17];
    const float* ln_g        = (const float*)d_in[18];
    const float* ln_b        = (const float*)d_in[19];

    const int* src = edge_index;
    const int* dst = edge_index + EE;

    static int once = 0;
    static cudaStream_t s2;
    static cudaEvent_t ev0, ev1;
    if (!once) {
        cudaFuncSetAttribute(tc_gemm<256>, cudaFuncAttributeMaxDynamicSharedMemorySize, 196608);
        cudaFuncSetAttribute(tc_gemm<256>, cudaFuncAttributePreferredSharedMemoryCarveout, 100);
        cudaFuncSetAttribute(tc_gemm<128>, cudaFuncAttributeMaxDynamicSharedMemorySize, 131072);
        cudaFuncSetAttribute(tc_gemm<128>, cudaFuncAttributePreferredSharedMemoryCarveout, 100);
        cudaStreamCreateWithFlags(&s2, cudaStreamNonBlocking);
        cudaEventCreateWithFlags(&ev0, cudaEventDisableTiming);
        cudaEventCreateWithFlags(&ev1, cudaEventDisableTiming);
        once = 1;
    }

    float *p_h, *p_qkvs, *p_agg, *p_bp;
    uint32_t *p_WTh, *p_WTm, *p_linTh, *p_linTm, *p_WeTh, *p_WeTm;
    uint32_t *p_xH, *p_xM, *p_hH, *p_hM, *p_sH, *p_sM;
    get_sym((void**)&p_h,     g_h);
    get_sym((void**)&p_qkvs,  g_qkvs);
    get_sym((void**)&p_agg,   g_agg);
    get_sym((void**)&p_bp,    g_bpack);
    get_sym((void**)&p_WTh,   g_WTh);
    get_sym((void**)&p_WTm,   g_WTm);
    get_sym((void**)&p_linTh, g_linTh);
    get_sym((void**)&p_linTm, g_linTm);
    get_sym((void**)&p_WeTh,  g_WeTh);
    get_sym((void**)&p_WeTm,  g_WeTm);
    get_sym((void**)&p_xH,    g_xH);
    get_sym((void**)&p_xM,    g_xM);
    get_sym((void**)&p_hH,    g_hH);
    get_sym((void**)&p_hM,    g_hM);
    get_sym((void**)&p_sH,    g_sH);
    get_sym((void**)&p_sM,    g_sM);

    const int MT = NP / 128;  // 157

    // ---- fork: CSR + time encoding on side stream, GEMM chain on main ----
    cudaEventRecord(ev0, 0);
    cudaStreamWaitEvent(s2, ev0, 0);
    k_zero_int<<<(NN + 255) / 256, 256, 0, s2>>>();
    k_count<<<(EE + 255) / 256, 256, 0, s2>>>(dst);
    k_scan<<<1, 1024, 0, s2>>>();
    k_place<<<(EE + 255) / 256, 256, 0, s2>>>(src, dst);
    k_te<<<(EE * 32 + 255) / 256, 256, 0, s2>>>(src, last_update, t, time_w, time_b);
    cudaEventRecord(ev1, s2);

    // main stream: prep + composite -> lin -> combined qkvsU(L0)
    k_prep<<<512, 256>>>(Wq, Wk, Wv, Wsk, bq, bk, bv, bsk, lin_w, We, x);
    {
        int total = NLAYER * 2 * 200 * 128 + NLAYER * 400;
        k_wu<<<(total + 255) / 256, 256>>>(Wq, bq, We);
    }

    tc_gemm<256><<<dim3(1, MT, 1), 512, 196608>>>(
        NN, 256, 64, p_xH, p_xM, 64, 0, p_linTh, p_linTm, 64, 0,
        lin_b, p_h, 256, 0, 0, p_hH, p_hM, 128, 256);

    tc_gemm<256><<<dim3(6, MT, 1), 512, 196608>>>(
        NN, 1424, 128, p_hH, p_hM, 128, 0,
        p_WTh, p_WTm, 128, 0,
        p_bp, p_qkvs, QROW, 0, 0, nullptr, nullptr, 0, 0);

    // join: k_edge needs CSR + te
    cudaStreamWaitEvent(0, ev1, 0);

    for (int L = 0; L < NLAYER; L++) {
        if (L > 0) {
            tc_gemm<256><<<dim3(6, MT, 1), 512, 196608>>>(
                NN, 1424, 128, p_hH, p_hM, 128, 0,
                p_WTh + (size_t)L * 1536 * 128, p_WTm + (size_t)L * 1536 * 128, 128, 0,
                p_bp + (size_t)L * 1536, p_qkvs, QROW, 0, 0, nullptr, nullptr, 0, 0);
        }

        k_edge<<<(NN * 32 + 255) / 256, 256>>>(msg);

        tc_gemm<128><<<dim3(1, MT, 2), 512, 131072>>>(
            NN, 128, 128, p_sH, p_sM, 128, NP * 128,
            p_WeTh + (size_t)L * 256 * 128, p_WeTm + (size_t)L * 256 * 128, 128, 128 * 128,
            nullptr, p_agg, 256, 128, 1, nullptr, nullptr, 0, 0);

        float* out_ptr = (L == NLAYER - 1) ? (float*)d_out : p_h;
        k_ln<<<NN, INC>>>(ln_g + (size_t)L * INC, ln_b + (size_t)L * INC,
                          out_ptr, (L < NLAYER - 1) ? 1 : 0);
    }
}

// round 16
// speedup vs baseline: 1.1523x; 1.1523x over previous
#include <cuda_runtime.h>
#include <cuda_bf16.h>
#include <math.h>
#include <float.h>
#include <stdint.h>

// ---------------- problem constants ----------------
#define NN 20000
#define NP 20096            // NN padded to 128
#define EE 320000
#define MEM 128
#define INC 256
#define HH 2
#define CC 128
#define ED 200
#define TD 100
#define NLAYER 3

static __device__ __constant__ float RSQRT_C = 0.08838834764831845f;

// ---------------- scratch (zero-initialized .bss pads are load-bearing) ----------------
__device__ float g_te   [(size_t)EE * TD];
__device__ float g_h    [(size_t)NN * INC];
__device__ float g_qkvs [(size_t)NN * 1024];
__device__ float g_U    [(size_t)NN * 2 * ED];
__device__ float g_agg  [(size_t)NN * INC];
__device__ int   g_deg [NN];
__device__ int   g_cnt [NN];
__device__ int   g_rowptr[NN + 1];
__device__ int2  g_epair[EE];      // (eid, src) packed
__device__ float g_bpack [(size_t)NLAYER * 1024];
// packed bf16 hi/lo pair buffers
__device__ uint32_t g_WTh [(size_t)NLAYER * 1024 * 128], g_WTm [(size_t)NLAYER * 1024 * 128];
__device__ uint32_t g_linTh[(size_t)256 * 64],           g_linTm[(size_t)256 * 64];
__device__ uint32_t g_WeH [(size_t)NLAYER * 256 * 128],  g_WeM [(size_t)NLAYER * 256 * 128];
__device__ uint32_t g_WeTh[(size_t)NLAYER * 256 * 128],  g_WeTm[(size_t)NLAYER * 256 * 128];
__device__ uint32_t g_xH  [(size_t)NP * 64],             g_xM  [(size_t)NP * 64];
__device__ uint32_t g_hH  [(size_t)NP * 128],            g_hM  [(size_t)NP * 128];
__device__ uint32_t g_qkvH[(size_t)NP * 512],            g_qkvM[(size_t)NP * 512];
__device__ uint32_t g_sH  [(size_t)2 * NP * 128],        g_sM  [(size_t)2 * NP * 128];

// ---------------- helpers ----------------
__device__ __forceinline__ uint32_t smem_u32(const void* p) {
    uint32_t a;
    asm("{ .reg .u64 t; cvta.to.shared.u64 t, %1; cvt.u32.u64 %0, t; }" : "=r"(a) : "l"(p));
    return a;
}
__device__ __forceinline__ uint32_t pack_hi(float x, float y) {
    __nv_bfloat162 p = __floats2bfloat162_rn(x, y);
    return *(uint32_t*)&p;
}
__device__ __forceinline__ uint32_t pack_mid(float x, float y) {
    __nv_bfloat16 hx = __float2bfloat16(x);
    __nv_bfloat16 hy = __float2bfloat16(y);
    __nv_bfloat162 p = __floats2bfloat162_rn(x - __bfloat162float(hx),
                                             y - __bfloat162float(hy));
    return *(uint32_t*)&p;
}
__device__ __forceinline__ void mma_bf16(float* c, const uint32_t* a,
                                         uint32_t b0, uint32_t b1) {
    asm volatile(
        "mma.sync.aligned.m16n8k16.row.col.f32.bf16.bf16.f32 "
        "{%0,%1,%2,%3}, {%4,%5,%6,%7}, {%8,%9}, {%0,%1,%2,%3};"
        : "+f"(c[0]), "+f"(c[1]), "+f"(c[2]), "+f"(c[3])
        : "r"(a[0]), "r"(a[1]), "r"(a[2]), "r"(a[3]), "r"(b0), "r"(b1));
}
__device__ __forceinline__ void ldsm4(uint32_t* r, uint32_t addr) {
    asm volatile("ldmatrix.sync.aligned.m8n8.x4.shared.b16 {%0,%1,%2,%3}, [%4];"
                 : "=r"(r[0]), "=r"(r[1]), "=r"(r[2]), "=r"(r[3]) : "r"(addr));
}
#define CP_ASYNC16(dst, src) \
    asm volatile("cp.async.cg.shared.global [%0], [%1], 16;" :: "r"(dst), "l"(src) : "memory")
#define CP_COMMIT asm volatile("cp.async.commit_group;" ::: "memory")
#define CP_WAIT1  asm volatile("cp.async.wait_group 1;" ::: "memory")

// fast accurate cos: Cody-Waite 2pi reduction + __cosf on reduced arg
__device__ __forceinline__ float fast_cos(float a) {
    const float INV2PI = 0.15915494309189535f;
    const float C1 = 6.28318548202514648f;
    const float C2 = -1.74845553e-7f;
    float k = rintf(a * INV2PI);
    float r = fmaf(-k, C1, a);
    r = fmaf(-k, C2, r);
    return __cosf(r);
}

// ---------------- HMMA 3xBF16 GEMM, BK=64, templated on BN (128 or 256) ----------------
template<int BN>
__global__ __launch_bounds__(512)
void tc_gemm(int M, int N, int K2,
             const uint32_t* __restrict__ AH, const uint32_t* __restrict__ AM,
             int lda2, int aZ,
             const uint32_t* __restrict__ BH, const uint32_t* __restrict__ BM,
             int ldb2, int bZ,
             const float* __restrict__ bias,
             float* __restrict__ C, int ldc, int cZ, int accum,
             uint32_t* __restrict__ auxH, uint32_t* __restrict__ auxM, int ldaux2,
             int auxN) {
    extern __shared__ uint32_t smem[];
    constexpr int NGRP = BN / 64;
    constexpr uint32_t STAGE = (128 + BN) * 256;
    const int tid = threadIdx.x;
    const int wid = tid >> 5;
    const int lane = tid & 31;
    const int wm = wid & 3;
    const int wn = wid >> 2;
    const int m0 = blockIdx.y * 128;
    const int n0 = blockIdx.x * BN;
    const int z = blockIdx.z;
    AH += (size_t)z * aZ; AM += (size_t)z * aZ;
    BH += (size_t)z * bZ; BM += (size_t)z * bZ;
    C  += (size_t)z * cZ;

    uint32_t sbase = smem_u32(smem);

    float c[2][2 * NGRP][4];
#pragma unroll
    for (int i = 0; i < 2; i++)
#pragma unroll
        for (int j = 0; j < 2 * NGRP; j++)
#pragma unroll
            for (int l = 0; l < 4; l++) c[i][j][l] = 0.f;

    const int nc = K2 >> 5;
    const uint32_t l7 = (uint32_t)(lane & 7);
    const uint32_t asel = (uint32_t)(lane >> 4);
    uint32_t aRowB[2];
#pragma unroll
    for (int mt = 0; mt < 2; mt++)
        aRowB[mt] = (uint32_t)(wm * 32 + mt * 16 + (lane & 15)) * 256u;
    const uint32_t bkb = (uint32_t)((lane >> 3) & 1);
    const uint32_t bOff0 = (uint32_t)(wn * (BN / 4) + (lane >> 4) * 8 + (int)l7) * 256u;

#define ISSUE(CH)                                                               \
    do {                                                                        \
        int k0p = (CH) << 5;                                                    \
        uint32_t stOff = (uint32_t)((CH) & 1) * STAGE;                          \
        _Pragma("unroll")                                                       \
        for (int it = 0; it < (128 + BN) / 32; it++) {                          \
            int idx = tid + it * 512;                                           \
            int row = idx >> 4;                                                 \
            int sb = idx & 15;                                                  \
            const uint32_t* S;                                                  \
            size_t rowOff;                                                      \
            if (row < 128) { S = (sb >> 3) ? AM : AH; rowOff = (size_t)(m0 + row) * lda2; } \
            else           { S = (sb >> 3) ? BM : BH; rowOff = (size_t)(n0 + row - 128) * ldb2; } \
            int pb = sb ^ (row & 7);                                            \
            CP_ASYNC16(sbase + stOff + (uint32_t)row * 256u + (uint32_t)pb * 16u, \
                       S + rowOff + k0p + (sb & 7) * 4);                        \
        }                                                                       \
    } while (0)

    ISSUE(0);
    CP_COMMIT;
    for (int ch = 0; ch < nc; ch++) {
        if (ch + 1 < nc) ISSUE(ch + 1);
        CP_COMMIT;
        CP_WAIT1;
        __syncthreads();
        const uint32_t Ab = sbase + (uint32_t)(ch & 1) * STAGE;
        const uint32_t Bb = Ab + 32768u;
#pragma unroll
        for (int ks = 0; ks < 4; ks++) {
            uint32_t abH = (asel + 2u * (uint32_t)ks) ^ l7;
            uint32_t abM = abH ^ 8u;
            uint32_t ah[2][4], am_[2][4];
#pragma unroll
            for (int mt = 0; mt < 2; mt++) {
                ldsm4(ah[mt],  Ab + aRowB[mt] + (abH << 4));
                ldsm4(am_[mt], Ab + aRowB[mt] + (abM << 4));
            }
            uint32_t bbH = (bkb + 2u * (uint32_t)ks) ^ l7;
            uint32_t bbM = bbH ^ 8u;
#pragma unroll
            for (int p2 = 0; p2 < NGRP; p2++) {
                uint32_t bh[4], bm[4];
                uint32_t bb = Bb + bOff0 + (uint32_t)p2 * 4096u;
                ldsm4(bh, bb + (bbH << 4));
                ldsm4(bm, bb + (bbM << 4));
#pragma unroll
                for (int sub = 0; sub < 2; sub++) {
                    int nt = 2 * p2 + sub;
                    uint32_t bh0 = bh[2 * sub], bh1 = bh[2 * sub + 1];
                    uint32_t bm0 = bm[2 * sub], bm1 = bm[2 * sub + 1];
#pragma unroll
                    for (int mt = 0; mt < 2; mt++) {
                        mma_bf16(c[mt][nt], ah[mt], bh0, bh1);
                        mma_bf16(c[mt][nt], ah[mt], bm0, bm1);
                        mma_bf16(c[mt][nt], am_[mt], bh0, bh1);
                    }
                }
            }
        }
        __syncthreads();
    }
#undef ISSUE

#pragma unroll
    for (int mt = 0; mt < 2; mt++) {
        int row0 = m0 + wm * 32 + mt * 16 + (lane >> 2);
#pragma unroll
        for (int nt = 0; nt < 2 * NGRP; nt++) {
            int col = n0 + wn * (BN / 4) + nt * 8 + 2 * (lane & 3);
            if (col >= N) continue;
#pragma unroll
            for (int half = 0; half < 2; half++) {
                int row = row0 + 8 * half;
                if (row >= M) continue;
                float v0 = c[mt][nt][2 * half];
                float v1 = c[mt][nt][2 * half + 1];
                if (bias) { v0 += bias[col]; v1 += bias[col + 1]; }
                size_t off = (size_t)row * ldc + col;
                if (accum) { v0 += C[off]; v1 += C[off + 1]; }
                C[off] = v0;
                C[off + 1] = v1;
                if (auxH && col < auxN) {
                    size_t po = (size_t)row * ldaux2 + (col >> 1);
                    auxH[po] = pack_hi(v0, v1);
                    auxM[po] = pack_mid(v0, v1);
                }
            }
        }
    }
}

// ---------------- weight / input pre-split ----------------
__global__ void k_prep(const float* __restrict__ Wq, const float* __restrict__ Wk,
                       const float* __restrict__ Wv, const float* __restrict__ Wsk,
                       const float* __restrict__ bq, const float* __restrict__ bk,
                       const float* __restrict__ bv, const float* __restrict__ bsk,
                       const float* __restrict__ lin_w, const float* __restrict__ We,
                       const float* __restrict__ x) {
    const int R1 = NLAYER * 1024 * 128;
    const int R2 = NLAYER * 1024;
    const int R3 = 256 * 64;
    const int R4 = NLAYER * 200 * 128;
    const int R5 = NLAYER * 256 * 100;
    const int R6 = NN * 64;
    int total = R1 + R2 + R3 + R4 + R5 + R6;
    for (int idx = blockIdx.x * blockDim.x + threadIdx.x; idx < total;
         idx += gridDim.x * blockDim.x) {
        int i = idx;
        if (i < R1) {
            int L = i / (1024 * 128);
            int rem = i - L * 1024 * 128;
            int row = rem >> 7, p = rem & 127;
            int which = row >> 8, n = row & 255;
            const float* W = (which == 0) ? Wq : (which == 1) ? Wk : (which == 2) ? Wv : Wsk;
            float v0 = W[(size_t)L * 65536 + (size_t)(2 * p) * 256 + n];
            float v1 = W[(size_t)L * 65536 + (size_t)(2 * p + 1) * 256 + n];
            g_WTh[i] = pack_hi(v0, v1);
            g_WTm[i] = pack_mid(v0, v1);
            continue;
        }
        i -= R1;
        if (i < R2) {
            int L = i / 1024, row = i - L * 1024;
            int which = row >> 8, n = row & 255;
            const float* bb = (which == 0) ? bq : (which == 1) ? bk : (which == 2) ? bv : bsk;
            g_bpack[i] = bb[L * 256 + n];
            continue;
        }
        i -= R2;
        if (i < R3) {
            int n = i >> 6, p = i & 63;
            float v0 = lin_w[(size_t)(2 * p) * 256 + n];
            float v1 = lin_w[(size_t)(2 * p + 1) * 256 + n];
            g_linTh[i] = pack_hi(v0, v1);
            g_linTm[i] = pack_mid(v0, v1);
            continue;
        }
        i -= R3;
        if (i < R4) {
            int L = i / (200 * 128);
            int rem = i - L * 200 * 128;
            int j = rem >> 7, p = rem & 127;
            float v0 = We[(size_t)L * 51200 + (size_t)j * 256 + 2 * p];
            float v1 = We[(size_t)L * 51200 + (size_t)j * 256 + 2 * p + 1];
            size_t o = ((size_t)L * 256 + j) * 128 + p;
            g_WeH[o] = pack_hi(v0, v1);
            g_WeM[o] = pack_mid(v0, v1);
            continue;
        }
        i -= R4;
        if (i < R5) {
            int L = i / (256 * 100);
            int rem = i - L * 256 * 100;
            int cch = rem / 100, p = rem - cch * 100;
            float v0 = We[(size_t)L * 51200 + (size_t)(2 * p) * 256 + cch];
            float v1 = We[(size_t)L * 51200 + (size_t)(2 * p + 1) * 256 + cch];
            size_t o = ((size_t)L * 256 + cch) * 128 + p;
            g_WeTh[o] = pack_hi(v0, v1);
            g_WeTm[o] = pack_mid(v0, v1);
            continue;
        }
        i -= R5;
        {
            int m = i >> 6, p = i & 63;
            float v0 = x[(size_t)m * 128 + 2 * p];
            float v1 = x[(size_t)m * 128 + 2 * p + 1];
            g_xH[i] = pack_hi(v0, v1);
            g_xM[i] = pack_mid(v0, v1);
        }
    }
}

// ---------------- CSR construction ----------------
__global__ void k_zero_int() {
    int i = blockIdx.x * blockDim.x + threadIdx.x;
    if (i < NN) { g_deg[i] = 0; g_cnt[i] = 0; }
}
__global__ void k_count(const int* __restrict__ dst) {
    int e = blockIdx.x * blockDim.x + threadIdx.x;
    if (e < EE) atomicAdd(&g_deg[dst[e]], 1);
}
__global__ void k_scan() {
    __shared__ int wsum[32];
    int tid = threadIdx.x;
    int lane = tid & 31;
    int wid = tid >> 5;
    int carry = 0;
    for (int base = 0; base < NN; base += 1024) {
        int i = base + tid;
        int x = (i < NN) ? g_deg[i] : 0;
#pragma unroll
        for (int o = 1; o < 32; o <<= 1) {
            int y = __shfl_up_sync(0xffffffffu, x, o);
            if (lane >= o) x += y;
        }
        if (lane == 31) wsum[wid] = x;
        __syncthreads();
        if (wid == 0) {
            int s = wsum[lane];
#pragma unroll
            for (int o = 1; o < 32; o <<= 1) {
                int y = __shfl_up_sync(0xffffffffu, s, o);
                if (lane >= o) s += y;
            }
            wsum[lane] = s;
        }
        __syncthreads();
        int off = (wid > 0) ? wsum[wid - 1] : 0;
        if (i < NN) g_rowptr[i + 1] = carry + off + x;
        carry += wsum[31];
        __syncthreads();
    }
    if (tid == 0) g_rowptr[0] = 0;
}
__global__ void k_place(const int* __restrict__ src, const int* __restrict__ dst) {
    int e = blockIdx.x * blockDim.x + threadIdx.x;
    if (e < EE) {
        int d = dst[e];
        int p = atomicAdd(&g_cnt[d], 1);
        g_epair[g_rowptr[d] + p] = make_int2(e, src[e]);
    }
}

// ---------------- time-encoding features: warp per edge, float4 stores ----------------
__global__ void k_te(const int* __restrict__ src,
                     const float* __restrict__ last_update,
                     const float* __restrict__ t,
                     const float* __restrict__ time_w,
                     const float* __restrict__ time_b) {
    int e = (blockIdx.x * blockDim.x + threadIdx.x) >> 5;
    int lane = threadIdx.x & 31;
    if (e >= EE) return;
    float rt = last_update[src[e]] - t[e];
    if (lane < 25) {
        float4 w = ((const float4*)time_w)[lane];
        float4 b = ((const float4*)time_b)[lane];
        float4 o;
        o.x = fast_cos(fmaf(rt, w.x, b.x));
        o.y = fast_cos(fmaf(rt, w.y, b.y));
        o.z = fast_cos(fmaf(rt, w.z, b.z));
        o.w = fast_cos(fmaf(rt, w.w, b.w));
        ((float4*)(g_te + (size_t)e * TD))[lane] = o;
    }
}

// ---------------- fused edge phase: warp per node, both heads, 2-edge unrolled ----
__global__ __launch_bounds__(256)
void k_edge(const float* __restrict__ msg) {
    int n = (blockIdx.x * blockDim.x + threadIdx.x) >> 5;
    int lane = threadIdx.x & 31;
    if (n >= NN) return;
    int b = g_rowptr[n], e_ = g_rowptr[n + 1];

    const float* qr = g_qkvs + (size_t)n * 1024;
    float q[8];
#pragma unroll
    for (int i = 0; i < 8; i++) q[i] = qr[lane + 32 * i];
    const float* Ur = g_U + (size_t)n * 400;
    float u0[7], u1[7];
#pragma unroll
    for (int i = 0; i < 7; i++) {
        int j = lane + 32 * i;
        u0[i] = (j < ED) ? Ur[j] : 0.f;
        u1[i] = (j < ED) ? Ur[ED + j] : 0.f;
    }

    float m0 = -FLT_MAX, m1 = -FLT_MAX, d0 = 0.f, d1 = 0.f;
    float vacc[8], s0[7], s1[7];
#pragma unroll
    for (int i = 0; i < 8; i++) vacc[i] = 0.f;
#pragma unroll
    for (int i = 0; i < 7; i++) { s0[i] = 0.f; s1[i] = 0.f; }

    int jj = b;
    for (; jj + 1 < e_; jj += 2) {
        int2 pA = g_epair[jj], pB = g_epair[jj + 1];
        int eA = pA.x, sA = pA.y;
        int eB = pB.x, sB = pB.y;
        const float* krA = g_qkvs + (size_t)sA * 1024 + 256;
        const float* krB = g_qkvs + (size_t)sB * 1024 + 256;
        float kvA[8], kvB[8], vvA[8], vvB[8], erA[7], erB[7];
#pragma unroll
        for (int i = 0; i < 8; i++) {
            kvA[i] = krA[lane + 32 * i];
            kvB[i] = krB[lane + 32 * i];
            vvA[i] = krA[256 + lane + 32 * i];
            vvB[i] = krB[256 + lane + 32 * i];
        }
        const float* teA = g_te + (size_t)eA * TD;
        const float* teB = g_te + (size_t)eB * TD;
        const float* mgA = msg + (size_t)eA * TD;
        const float* mgB = msg + (size_t)eB * TD;
#pragma unroll
        for (int i = 0; i < 7; i++) {
            int j = lane + 32 * i;
            erA[i] = (j < ED) ? ((j < TD) ? teA[j] : mgA[j - TD]) : 0.f;
            erB[i] = (j < ED) ? ((j < TD) ? teB[j] : mgB[j - TD]) : 0.f;
        }
        float aA0 = 0.f, aA1 = 0.f, aB0 = 0.f, aB1 = 0.f;
#pragma unroll
        for (int i = 0; i < 4; i++) {
            aA0 += q[i] * kvA[i];       aA1 += q[i + 4] * kvA[i + 4];
            aB0 += q[i] * kvB[i];       aB1 += q[i + 4] * kvB[i + 4];
        }
#pragma unroll
        for (int i = 0; i < 7; i++) {
            aA0 += erA[i] * u0[i];      aA1 += erA[i] * u1[i];
            aB0 += erB[i] * u0[i];      aB1 += erB[i] * u1[i];
        }
#pragma unroll
        for (int o = 16; o; o >>= 1) {
            aA0 += __shfl_xor_sync(0xffffffffu, aA0, o);
            aA1 += __shfl_xor_sync(0xffffffffu, aA1, o);
            aB0 += __shfl_xor_sync(0xffffffffu, aB0, o);
            aB1 += __shfl_xor_sync(0xffffffffu, aB1, o);
        }
        aA0 *= RSQRT_C; aA1 *= RSQRT_C; aB0 *= RSQRT_C; aB1 *= RSQRT_C;

        float mn0 = fmaxf(m0, fmaxf(aA0, aB0));
        float sc0 = expf(m0 - mn0);
        float wA0 = expf(aA0 - mn0);
        float wB0 = expf(aB0 - mn0);
        d0 = d0 * sc0 + wA0 + wB0;
        m0 = mn0;
        float mn1 = fmaxf(m1, fmaxf(aA1, aB1));
        float sc1 = expf(m1 - mn1);
        float wA1 = expf(aA1 - mn1);
        float wB1 = expf(aB1 - mn1);
        d1 = d1 * sc1 + wA1 + wB1;
        m1 = mn1;
#pragma unroll
        for (int i = 0; i < 4; i++) {
            vacc[i]     = vacc[i]     * sc0 + wA0 * vvA[i]     + wB0 * vvB[i];
            vacc[i + 4] = vacc[i + 4] * sc1 + wA1 * vvA[i + 4] + wB1 * vvB[i + 4];
        }
#pragma unroll
        for (int i = 0; i < 7; i++) {
            s0[i] = s0[i] * sc0 + wA0 * erA[i] + wB0 * erB[i];
            s1[i] = s1[i] * sc1 + wA1 * erA[i] + wB1 * erB[i];
        }
    }
    if (jj < e_) {
        int2 pA = g_epair[jj];
        int eA = pA.x, sA = pA.y;
        const float* krA = g_qkvs + (size_t)sA * 1024 + 256;
        float kvA[8], vvA[8], erA[7];
#pragma unroll
        for (int i = 0; i < 8; i++) {
            kvA[i] = krA[lane + 32 * i];
            vvA[i] = krA[256 + lane + 32 * i];
        }
        const float* teA = g_te + (size_t)eA * TD;
        const float* mgA = msg + (size_t)eA * TD;
#pragma unroll
        for (int i = 0; i < 7; i++) {
            int j = lane + 32 * i;
            erA[i] = (j < ED) ? ((j < TD) ? teA[j] : mgA[j - TD]) : 0.f;
        }
        float aA0 = 0.f, aA1 = 0.f;
#pragma unroll
        for (int i = 0; i < 4; i++) { aA0 += q[i] * kvA[i]; aA1 += q[i + 4] * kvA[i + 4]; }
#pragma unroll
        for (int i = 0; i < 7; i++) { aA0 += erA[i] * u0[i]; aA1 += erA[i] * u1[i]; }
#pragma unroll
        for (int o = 16; o; o >>= 1) {
            aA0 += __shfl_xor_sync(0xffffffffu, aA0, o);
            aA1 += __shfl_xor_sync(0xffffffffu, aA1, o);
        }
        aA0 *= RSQRT_C; aA1 *= RSQRT_C;
        float mn0 = fmaxf(m0, aA0);
        float sc0 = expf(m0 - mn0);
        float wA0 = expf(aA0 - mn0);
        d0 = d0 * sc0 + wA0;
        m0 = mn0;
        float mn1 = fmaxf(m1, aA1);
        float sc1 = expf(m1 - mn1);
        float wA1 = expf(aA1 - mn1);
        d1 = d1 * sc1 + wA1;
        m1 = mn1;
#pragma unroll
        for (int i = 0; i < 4; i++) {
            vacc[i]     = vacc[i]     * sc0 + wA0 * vvA[i];
            vacc[i + 4] = vacc[i + 4] * sc1 + wA1 * vvA[i + 4];
        }
#pragma unroll
        for (int i = 0; i < 7; i++) {
            s0[i] = s0[i] * sc0 + wA0 * erA[i];
            s1[i] = s1[i] * sc1 + wA1 * erA[i];
        }
    }

    float div0 = 1.f / (d0 + 1e-16f);
    float div1 = 1.f / (d1 + 1e-16f);
    float* ar = g_agg + (size_t)n * 256;
#pragma unroll
    for (int i = 0; i < 4; i++) {
        ar[lane + 32 * i]         = vacc[i] * div0;
        ar[lane + 32 * (i + 4)]   = vacc[i + 4] * div1;
    }
#pragma unroll
    for (int i = 0; i < 7; i++) {
        int j = lane + 32 * i;
        float v0 = (j < ED) ? s0[i] * div0 : 0.f;
        float v1 = (j < ED) ? s1[i] * div1 : 0.f;
        float v0b = __shfl_xor_sync(0xffffffffu, v0, 1);
        float v1b = __shfl_xor_sync(0xffffffffu, v1, 1);
        if (!(lane & 1) && j < ED) {
            size_t o0 = (size_t)n * 128 + (j >> 1);
            g_sH[o0] = pack_hi(v0, v0b);
            g_sM[o0] = pack_mid(v0, v0b);
            size_t o1 = ((size_t)NP + n) * 128 + (j >> 1);
            g_sH[o1] = pack_hi(v1, v1b);
            g_sM[o1] = pack_mid(v1, v1b);
        }
    }
}

// ---------------- residual + LayerNorm (+ SiLU, + bf16 pair emit), warp-shuffle ----
__global__ void k_ln(const float* __restrict__ ln_g, const float* __restrict__ ln_b,
                     float* __restrict__ out, int silu) {
    __shared__ float red[8];
    __shared__ float bc[2];
    int n = blockIdx.x;
    int c = threadIdx.x;
    int lane = c & 31;
    int w = c >> 5;
    size_t off = (size_t)n * INC + c;
    float pre = g_h[off] + g_agg[off] + g_qkvs[(size_t)n * 1024 + 768 + c];

    float s = pre;
#pragma unroll
    for (int o = 16; o; o >>= 1) s += __shfl_xor_sync(0xffffffffu, s, o);
    if (lane == 0) red[w] = s;
    __syncthreads();
    if (w == 0) {
        float t2 = (lane < 8) ? red[lane] : 0.f;
#pragma unroll
        for (int o = 4; o; o >>= 1) t2 += __shfl_xor_sync(0xffffffffu, t2, o);
        if (lane == 0) bc[0] = t2 * (1.f / INC);
    }
    __syncthreads();
    float mu = bc[0];
    float dv = pre - mu;
    float s2 = dv * dv;
#pragma unroll
    for (int o = 16; o; o >>= 1) s2 += __shfl_xor_sync(0xffffffffu, s2, o);
    if (lane == 0) red[w] = s2;
    __syncthreads();
    if (w == 0) {
        float t2 = (lane < 8) ? red[lane] : 0.f;
#pragma unroll
        for (int o = 4; o; o >>= 1) t2 += __shfl_xor_sync(0xffffffffu, t2, o);
        if (lane == 0) bc[1] = rsqrtf(t2 * (1.f / INC) + 1e-5f);
    }
    __syncthreads();
    float y = dv * bc[1] * ln_g[c] + ln_b[c];
    if (silu) {
        y = y / (1.f + expf(-y));
        float y2 = __shfl_xor_sync(0xffffffffu, y, 1);
        out[off] = y;
        if (!(c & 1)) {
            size_t po = (size_t)n * 128 + (c >> 1);
            g_hH[po] = pack_hi(y, y2);
            g_hM[po] = pack_mid(y, y2);
        }
    } else {
        out[off] = y;
    }
}

// ---------------- host launcher ----------------
static inline void get_sym(void** p, const void* sym) { cudaGetSymbolAddress(p, sym); }

extern "C" void kernel_launch(void* const* d_in, const int* in_sizes, int n_in,
                              void* d_out, int out_size) {
    const float* x           = (const float*)d_in[0];
    const float* last_update = (const float*)d_in[1];
    const int*   edge_index  = (const int*)  d_in[2];
    const float* t           = (const float*)d_in[3];
    const float* msg         = (const float*)d_in[4];
    const float* time_w      = (const float*)d_in[5];
    const float* time_b      = (const float*)d_in[6];
    const float* lin_w       = (const float*)d_in[7];
    const float* lin_b       = (const float*)d_in[8];
    const float* Wq          = (const float*)d_in[9];
    const float* bq          = (const float*)d_in[10];
    const float* Wk          = (const float*)d_in[11];
    const float* bk          = (const float*)d_in[12];
    const float* Wv          = (const float*)d_in[13];
    const float* bv          = (const float*)d_in[14];
    const float* We          = (const float*)d_in[15];
    const float* Wsk         = (const float*)d_in[16];
    const float* bsk         = (const float*)d_in[17];
    const float* ln_g        = (const float*)d_in[18];
    const float* ln_b        = (const float*)d_in[19];

    const int* src = edge_index;
    const int* dst = edge_index + EE;

    static int once = 0;
    static cudaStream_t s2;
    static cudaEvent_t ev0, ev1;
    if (!once) {
        cudaFuncSetAttribute(tc_gemm<256>, cudaFuncAttributeMaxDynamicSharedMemorySize, 196608);
        cudaFuncSetAttribute(tc_gemm<256>, cudaFuncAttributePreferredSharedMemoryCarveout, 100);
        cudaFuncSetAttribute(tc_gemm<128>, cudaFuncAttributeMaxDynamicSharedMemorySize, 131072);
        cudaFuncSetAttribute(tc_gemm<128>, cudaFuncAttributePreferredSharedMemoryCarveout, 100);
        cudaStreamCreateWithFlags(&s2, cudaStreamNonBlocking);
        cudaEventCreateWithFlags(&ev0, cudaEventDisableTiming);
        cudaEventCreateWithFlags(&ev1, cudaEventDisableTiming);
        once = 1;
    }

    float *p_h, *p_qkvs, *p_U, *p_agg, *p_bp;
    uint32_t *p_WTh, *p_WTm, *p_linTh, *p_linTm, *p_WeH, *p_WeM, *p_WeTh, *p_WeTm;
    uint32_t *p_xH, *p_xM, *p_hH, *p_hM, *p_qkvH, *p_qkvM, *p_sH, *p_sM;
    get_sym((void**)&p_h,     g_h);
    get_sym((void**)&p_qkvs,  g_qkvs);
    get_sym((void**)&p_U,     g_U);
    get_sym((void**)&p_agg,   g_agg);
    get_sym((void**)&p_bp,    g_bpack);
    get_sym((void**)&p_WTh,   g_WTh);
    get_sym((void**)&p_WTm,   g_WTm);
    get_sym((void**)&p_linTh, g_linTh);
    get_sym((void**)&p_linTm, g_linTm);
    get_sym((void**)&p_WeH,   g_WeH);
    get_sym((void**)&p_WeM,   g_WeM);
    get_sym((void**)&p_WeTh,  g_WeTh);
    get_sym((void**)&p_WeTm,  g_WeTm);
    get_sym((void**)&p_xH,    g_xH);
    get_sym((void**)&p_xM,    g_xM);
    get_sym((void**)&p_hH,    g_hH);
    get_sym((void**)&p_hM,    g_hM);
    get_sym((void**)&p_qkvH,  g_qkvH);
    get_sym((void**)&p_qkvM,  g_qkvM);
    get_sym((void**)&p_sH,    g_sH);
    get_sym((void**)&p_sM,    g_sM);

    const int MT = NP / 128;  // 157

    // ---- fork: CSR + time encoding on side stream, GEMM chain on main ----
    cudaEventRecord(ev0, 0);
    cudaStreamWaitEvent(s2, ev0, 0);
    k_zero_int<<<(NN + 255) / 256, 256, 0, s2>>>();
    k_count<<<(EE + 255) / 256, 256, 0, s2>>>(dst);
    k_scan<<<1, 1024, 0, s2>>>();
    k_place<<<(EE + 255) / 256, 256, 0, s2>>>(src, dst);
    k_te<<<(EE * 32 + 255) / 256, 256, 0, s2>>>(src, last_update, t, time_w, time_b);
    cudaEventRecord(ev1, s2);

    // main stream: prep -> lin -> qkvs(L0) -> U(L0)
    k_prep<<<512, 256>>>(Wq, Wk, Wv, Wsk, bq, bk, bv, bsk, lin_w, We, x);

    tc_gemm<256><<<dim3(1, MT, 1), 512, 196608>>>(
        NN, 256, 64, p_xH, p_xM, 64, 0, p_linTh, p_linTm, 64, 0,
        lin_b, p_h, 256, 0, 0, p_hH, p_hM, 128, 256);

    tc_gemm<256><<<dim3(4, MT, 1), 512, 196608>>>(
        NN, 1024, 128, p_hH, p_hM, 128, 0,
        p_WTh, p_WTm, 128, 0,
        p_bp, p_qkvs, 1024, 0, 0, p_qkvH, p_qkvM, 512, 256);

    tc_gemm<256><<<dim3(1, MT, 2), 512, 196608>>>(
        NN, 200, 64, p_qkvH, p_qkvM, 512, 64,
        p_WeH, p_WeM, 128, 64,
        nullptr, p_U, 400, 200, 0, nullptr, nullptr, 0, 0);

    // join: k_edge needs CSR + te
    cudaStreamWaitEvent(0, ev1, 0);

    for (int L = 0; L < NLAYER; L++) {
        if (L > 0) {
            tc_gemm<256><<<dim3(4, MT, 1), 512, 196608>>>(
                NN, 1024, 128, p_hH, p_hM, 128, 0,
                p_WTh + (size_t)L * 1024 * 128, p_WTm + (size_t)L * 1024 * 128, 128, 0,
                p_bp + (size_t)L * 1024, p_qkvs, 1024, 0, 0, p_qkvH, p_qkvM, 512, 256);

            tc_gemm<256><<<dim3(1, MT, 2), 512, 196608>>>(
                NN, 200, 64, p_qkvH, p_qkvM, 512, 64,
                p_WeH + (size_t)L * 256 * 128, p_WeM + (size_t)L * 256 * 128, 128, 64,
                nullptr, p_U, 400, 200, 0, nullptr, nullptr, 0, 0);
        }

        k_edge<<<(NN * 32 + 255) / 256, 256>>>(msg);

        tc_gemm<128><<<dim3(1, MT, 2), 512, 131072>>>(
            NN, 128, 128, p_sH, p_sM, 128, NP * 128,
            p_WeTh + (size_t)L * 256 * 128, p_WeTm + (size_t)L * 256 * 128, 128, 128 * 128,
            nullptr, p_agg, 256, 128, 1, nullptr, nullptr, 0, 0);

        float* out_ptr = (L == NLAYER - 1) ? (float*)d_out : p_h;
        k_ln<<<NN, INC>>>(ln_g + (size_t)L * INC, ln_b + (size_t)L * INC,
                          out_ptr, (L < NLAYER - 1) ? 1 : 0);
    }
}